// round 1
// baseline (speedup 1.0000x reference)
#include <cuda_runtime.h>
#include <cstdint>

#define MM 128
#define DD 5
#define FA 62
#define FB 6
#define FAN 68
#define CC 128

// shared memory layout (float offsets)
#define S_ATOMS 0
#define S_X     (MM*FA)            /* 7936  */
#define S_W     (S_X + MM*FAN)     /* 16640 */
#define S_BS    (S_W + FAN*CC)     /* 25344 */
#define S_DEG   (S_BS + CC)        /* 25472 */
#define S_FLOATS (S_DEG + MM)      /* 25600 */
#define SMEM_BYTES (S_FLOATS * 4)  /* 102400 */

typedef unsigned long long u64;

__device__ __forceinline__ u64 pack2(float lo, float hi) {
    u64 r; asm("mov.b64 %0,{%1,%2};" : "=l"(r) : "f"(lo), "f"(hi)); return r;
}
__device__ __forceinline__ void unpack2(u64 v, float& lo, float& hi) {
    asm("mov.b64 {%0,%1},%2;" : "=f"(lo), "=f"(hi) : "l"(v));
}
// packed dual fp32 FMA (sm_100+): d.lo = a.lo*b.lo+c.lo ; d.hi = a.hi*b.hi+c.hi
__device__ __forceinline__ u64 fma2(u64 a, u64 b, u64 c) {
    u64 d; asm("fma.rn.f32x2 %0,%1,%2,%3;" : "=l"(d) : "l"(a), "l"(b), "l"(c)); return d;
}

__global__ __launch_bounds__(256, 2)
void tga_kernel(const float* __restrict__ atoms,
                const float* __restrict__ bonds,
                const int*   __restrict__ edges,
                const float* __restrict__ Wi,   // (D, FAN, CC)
                const float* __restrict__ bi,   // (D, CC)
                const float* __restrict__ Ws,   // (FAN, CC)
                const float* __restrict__ bs,   // (CC)
                float* __restrict__ out)        // (B, MM, CC)
{
    extern __shared__ float sm[];
    float* s_atoms = sm + S_ATOMS;   // atoms[b]: [MM][FA]
    float* s_X     = sm + S_X;       // summed features sf: [MM][FAN]
    float* s_W     = sm + S_W;       // W_self: [FAN][CC]
    float* s_bs    = sm + S_BS;      // b_self: [CC]
    int*   s_deg   = (int*)(sm + S_DEG);

    const int b    = blockIdx.x;
    const int tid  = threadIdx.x;
    const int w    = tid >> 5;
    const int lane = tid & 31;

    // ---- cooperative staging: atoms[b] and W_self into smem ----
    const float* ga = atoms + (size_t)b * (MM * FA);
    for (int i = tid; i < (MM * FA) / 4; i += 256)
        ((float4*)s_atoms)[i] = ((const float4*)ga)[i];
    for (int i = tid; i < (FAN * CC) / 4; i += 256)
        ((float4*)s_W)[i] = ((const float4*)Ws)[i];
    if (tid < CC) s_bs[tid] = bs[tid];
    __syncthreads();

    // ---- gather phase: warp w owns nodes [16w, 16w+16) ----
    const int*   ge = edges + (size_t)b * (MM * DD);
    const float* gb = bonds + (size_t)b * (MM * DD * FB);

    for (int mi = 0; mi < 16; mi++) {
        const int m = w * 16 + mi;
        const int e0 = ge[m*DD+0], e1 = ge[m*DD+1], e2 = ge[m*DD+2],
                  e3 = ge[m*DD+3], e4 = ge[m*DD+4];
        if (lane == 0)
            s_deg[m] = (e0>=0) + (e1>=0) + (e2>=0) + (e3>=0) + (e4>=0);
        #pragma unroll
        for (int rep = 0; rep < 2; rep++) {
            const int f = lane + rep * 32;
            if (f < FA) {
                float s = 0.f;
                if (e0 >= 0) s += s_atoms[e0*FA + f];
                if (e1 >= 0) s += s_atoms[e1*FA + f];
                if (e2 >= 0) s += s_atoms[e2*FA + f];
                if (e3 >= 0) s += s_atoms[e3*FA + f];
                if (e4 >= 0) s += s_atoms[e4*FA + f];
                s_X[m*FAN + f] = s;
            }
        }
        if (lane < FB) {
            const float* bp = gb + m * (DD*FB) + lane;
            s_X[m*FAN + FA + lane] = bp[0] + bp[6] + bp[12] + bp[18] + bp[24];
        }
    }
    __syncwarp();   // X/deg written and read by the SAME warp only

    // ---- compute phase: warp w, 4 chunks of 4 nodes; lane owns 4 cols ----
    const int c0 = lane * 4;
    const float bias0 = s_bs[c0+0], bias1 = s_bs[c0+1],
                bias2 = s_bs[c0+2], bias3 = s_bs[c0+3];

    for (int chunk = 0; chunk < 4; chunk++) {
        const int mbase = w * 16 + chunk * 4;
        // acc[n][c]: f32x2, lo accumulates even-k products (+bias), hi odd-k
        u64 acc[4][4];
        #pragma unroll
        for (int n = 0; n < 4; n++) {
            acc[n][0] = pack2(bias0, 0.f);
            acc[n][1] = pack2(bias1, 0.f);
            acc[n][2] = pack2(bias2, 0.f);
            acc[n][3] = pack2(bias3, 0.f);
        }

        // vxi[k] for k<62 is atoms row
        #pragma unroll 2
        for (int k = 0; k < FA; k += 2) {
            const float4 w0 = *(const float4*)(s_W + (k  )*CC + c0);
            const float4 w1 = *(const float4*)(s_W + (k+1)*CC + c0);
            const u64 wp0 = pack2(w0.x, w1.x);
            const u64 wp1 = pack2(w0.y, w1.y);
            const u64 wp2 = pack2(w0.z, w1.z);
            const u64 wp3 = pack2(w0.w, w1.w);
            #pragma unroll
            for (int n = 0; n < 4; n++) {
                const u64 xp = *(const u64*)(s_atoms + (mbase+n)*FA + k);
                acc[n][0] = fma2(xp, wp0, acc[n][0]);
                acc[n][1] = fma2(xp, wp1, acc[n][1]);
                acc[n][2] = fma2(xp, wp2, acc[n][2]);
                acc[n][3] = fma2(xp, wp3, acc[n][3]);
            }
        }
        // vxi[k] for k in [62,68) is summed_bonds == sf[62:68] (shared with X)
        #pragma unroll
        for (int k = FA; k < FAN; k += 2) {
            const float4 w0 = *(const float4*)(s_W + (k  )*CC + c0);
            const float4 w1 = *(const float4*)(s_W + (k+1)*CC + c0);
            const u64 wp0 = pack2(w0.x, w1.x);
            const u64 wp1 = pack2(w0.y, w1.y);
            const u64 wp2 = pack2(w0.z, w1.z);
            const u64 wp3 = pack2(w0.w, w1.w);
            #pragma unroll
            for (int n = 0; n < 4; n++) {
                const u64 xp = *(const u64*)(s_X + (mbase+n)*FAN + k);
                acc[n][0] = fma2(xp, wp0, acc[n][0]);
                acc[n][1] = fma2(xp, wp1, acc[n][1]);
                acc[n][2] = fma2(xp, wp2, acc[n][2]);
                acc[n][3] = fma2(xp, wp3, acc[n][3]);
            }
        }

        // epilogue per node: relu(self) [+ relu(inner matvec) when deg < 5]
        #pragma unroll 1
        for (int n = 0; n < 4; n++) {
            const int m = mbase + n;
            float r0, r1, r2, r3;
            { float lo, hi; unpack2(acc[n][0], lo, hi); r0 = fmaxf(lo + hi, 0.f); }
            { float lo, hi; unpack2(acc[n][1], lo, hi); r1 = fmaxf(lo + hi, 0.f); }
            { float lo, hi; unpack2(acc[n][2], lo, hi); r2 = fmaxf(lo + hi, 0.f); }
            { float lo, hi; unpack2(acc[n][3], lo, hi); r3 = fmaxf(lo + hi, 0.f); }

            const int deg = s_deg[m];            // warp-uniform branch
            if (deg < DD) {
                const float* wp = Wi + (size_t)deg * (FAN * CC) + c0;
                const float4 bi4 = *(const float4*)(bi + deg * CC + c0);
                u64 i0 = pack2(bi4.x, 0.f), i1 = pack2(bi4.y, 0.f),
                    i2 = pack2(bi4.z, 0.f), i3 = pack2(bi4.w, 0.f);
                #pragma unroll 2
                for (int k = 0; k < FAN; k += 2) {
                    const float4 w0 = *(const float4*)(wp + (k  )*CC);
                    const float4 w1 = *(const float4*)(wp + (k+1)*CC);
                    const u64 xp = *(const u64*)(s_X + m*FAN + k);
                    i0 = fma2(xp, pack2(w0.x, w1.x), i0);
                    i1 = fma2(xp, pack2(w0.y, w1.y), i1);
                    i2 = fma2(xp, pack2(w0.z, w1.z), i2);
                    i3 = fma2(xp, pack2(w0.w, w1.w), i3);
                }
                { float lo, hi; unpack2(i0, lo, hi); r0 += fmaxf(lo + hi, 0.f); }
                { float lo, hi; unpack2(i1, lo, hi); r1 += fmaxf(lo + hi, 0.f); }
                { float lo, hi; unpack2(i2, lo, hi); r2 += fmaxf(lo + hi, 0.f); }
                { float lo, hi; unpack2(i3, lo, hi); r3 += fmaxf(lo + hi, 0.f); }
            }

            float4 o; o.x = r0; o.y = r1; o.z = r2; o.w = r3;
            *(float4*)(out + ((size_t)b * MM + m) * CC + c0) = o;
        }
    }
}

extern "C" void kernel_launch(void* const* d_in, const int* in_sizes, int n_in,
                              void* d_out, int out_size) {
    const float* atoms = (const float*)d_in[0];
    const float* bonds = (const float*)d_in[1];
    const int*   edges = (const int*)  d_in[2];
    const float* Wi    = (const float*)d_in[3];
    const float* bi    = (const float*)d_in[4];
    const float* Ws    = (const float*)d_in[5];
    const float* bs    = (const float*)d_in[6];
    float* out = (float*)d_out;

    const int B = in_sizes[0] / (MM * FA);

    cudaFuncSetAttribute(tga_kernel,
                         cudaFuncAttributeMaxDynamicSharedMemorySize, SMEM_BYTES);
    tga_kernel<<<B, 256, SMEM_BYTES>>>(atoms, bonds, edges, Wi, bi, Ws, bs, out);
}

// round 2
// speedup vs baseline: 1.0585x; 1.0585x over previous
#include <cuda_runtime.h>
#include <cstdint>

#define MM 128
#define DD 5
#define FA 62
#define FB 6
#define FAN 68
#define CC 128
#define NKQ 17   /* 68 / 4 k-quads */

// shared memory layout (float offsets)
#define S_V    0                       /* vxi  = [atoms | summed_bonds] : [MM][FAN] */
#define S_X    (MM*FAN)                /* summed features               : [MM][FAN] */
#define S_WP   (S_X + MM*FAN)         /* W_self packed f32x2 [34][CC] u64 (= FAN*CC floats) */
#define S_BS   (S_WP + FAN*CC)
#define S_DEG  (S_BS + CC)
#define S_EDG  (S_DEG + MM)
#define S_TOT  (S_EDG + MM*DD)
#define SMEM_BYTES (S_TOT * 4)         /* 108,032 B -> 2 CTAs/SM */

typedef unsigned long long u64;

__device__ __forceinline__ u64 pack2(float lo, float hi) {
    u64 r; asm("mov.b64 %0,{%1,%2};" : "=l"(r) : "f"(lo), "f"(hi)); return r;
}
__device__ __forceinline__ void unpack2(u64 v, float& lo, float& hi) {
    asm("mov.b64 {%0,%1},%2;" : "=f"(lo), "=f"(hi) : "l"(v));
}
// packed dual fp32 FMA (sm_100+)
__device__ __forceinline__ u64 fma2(u64 a, u64 b, u64 c) {
    u64 d; asm("fma.rn.f32x2 %0,%1,%2,%3;" : "=l"(d) : "l"(a), "l"(b), "l"(c)); return d;
}

__global__ __launch_bounds__(256, 2)
void tga_kernel(const float* __restrict__ atoms,
                const float* __restrict__ bonds,
                const int*   __restrict__ edges,
                const float* __restrict__ Wi,   // (D, FAN, CC)
                const float* __restrict__ bi,   // (D, CC)
                const float* __restrict__ Ws,   // (FAN, CC)
                const float* __restrict__ bs,   // (CC)
                float* __restrict__ out)        // (B, MM, CC)
{
    extern __shared__ float sm[];
    float* s_V   = sm + S_V;
    float* s_X   = sm + S_X;
    u64*   s_Wp  = (u64*)(sm + S_WP);
    float* s_bs  = sm + S_BS;
    int*   s_deg = (int*)(sm + S_DEG);
    int*   s_edg = (int*)(sm + S_EDG);

    const int b    = blockIdx.x;
    const int tid  = threadIdx.x;
    const int w    = tid >> 5;
    const int lane = tid & 31;

    const float* ga = atoms + (size_t)b * (MM * FA);
    const float* gb = bonds + (size_t)b * (MM * DD * FB);
    const int*   ge = edges + (size_t)b * (MM * DD);

    // ---- phase 1: cooperative staging ----
    // atoms -> s_V[m][0:62]
    for (int i = tid; i < MM * FA; i += 256) {
        const int m = i / FA, f = i - m * FA;
        s_V[m * FAN + f] = ga[i];
    }
    // summed bonds -> s_V[m][62:68] and s_X[m][62:68]
    for (int i = tid; i < MM * FB; i += 256) {
        const int m = i / FB, f = i - m * FB;
        const float* bp = gb + m * (DD * FB) + f;
        const float s = bp[0] + bp[6] + bp[12] + bp[18] + bp[24];
        s_V[m * FAN + FA + f] = s;
        s_X[m * FAN + FA + f] = s;
    }
    // W_self -> f32x2-packed: s_Wp[kp*CC + c] = (Ws[2kp][c], Ws[2kp+1][c])
    for (int i = tid; i < (FAN / 2) * CC; i += 256) {
        const int kp = i >> 7, c = i & 127;
        s_Wp[i] = pack2(Ws[(2 * kp) * CC + c], Ws[(2 * kp + 1) * CC + c]);
    }
    if (tid < CC) s_bs[tid] = bs[tid];
    for (int i = tid; i < MM * DD; i += 256) s_edg[i] = ge[i];
    __syncthreads();

    // ---- phase 2: per-warp neighbor gather; warp w owns nodes [16w,16w+16) ----
    for (int mi = 0; mi < 16; mi++) {
        const int m = w * 16 + mi;
        const int e0 = s_edg[m*DD+0], e1 = s_edg[m*DD+1], e2 = s_edg[m*DD+2],
                  e3 = s_edg[m*DD+3], e4 = s_edg[m*DD+4];
        if (lane == 0)
            s_deg[m] = (e0>=0) + (e1>=0) + (e2>=0) + (e3>=0) + (e4>=0);
        #pragma unroll
        for (int rep = 0; rep < 2; rep++) {
            const int f = lane + rep * 32;
            if (f < FA) {
                float s = 0.f;
                if (e0 >= 0) s += s_V[e0*FAN + f];
                if (e1 >= 0) s += s_V[e1*FAN + f];
                if (e2 >= 0) s += s_V[e2*FAN + f];
                if (e3 >= 0) s += s_V[e3*FAN + f];
                if (e4 >= 0) s += s_V[e4*FAN + f];
                s_X[m*FAN + f] = s;
            }
        }
    }
    __syncwarp();   // X/deg written and read by the SAME warp only

    // ---- phase 3: self matvec, 2 chunks of 8 nodes; lane owns 4 cols ----
    const int c0 = lane * 4;
    const float bias0 = s_bs[c0+0], bias1 = s_bs[c0+1],
                bias2 = s_bs[c0+2], bias3 = s_bs[c0+3];

    for (int chunk = 0; chunk < 2; chunk++) {
        const int mbase = w * 16 + chunk * 8;
        u64 acc[8][4];
        #pragma unroll
        for (int n = 0; n < 8; n++) {
            acc[n][0] = pack2(bias0, 0.f);
            acc[n][1] = pack2(bias1, 0.f);
            acc[n][2] = pack2(bias2, 0.f);
            acc[n][3] = pack2(bias3, 0.f);
        }

        #pragma unroll 1
        for (int kq = 0; kq < NKQ; kq++) {
            // weights for k = 4kq .. 4kq+3 at this lane's 4 columns
            const u64* wrA = s_Wp + (2*kq    ) * CC + c0;
            const u64* wrB = s_Wp + (2*kq + 1) * CC + c0;
            const ulonglong2 wA0 = *(const ulonglong2*)(wrA);
            const ulonglong2 wA1 = *(const ulonglong2*)(wrA + 2);
            const ulonglong2 wB0 = *(const ulonglong2*)(wrB);
            const ulonglong2 wB1 = *(const ulonglong2*)(wrB + 2);
            const float* xb = s_V + kq * 4;
            #pragma unroll
            for (int n = 0; n < 8; n++) {
                const ulonglong2 xv = *(const ulonglong2*)(xb + (mbase + n) * FAN);
                acc[n][0] = fma2(xv.x, wA0.x, acc[n][0]);
                acc[n][1] = fma2(xv.x, wA0.y, acc[n][1]);
                acc[n][2] = fma2(xv.x, wA1.x, acc[n][2]);
                acc[n][3] = fma2(xv.x, wA1.y, acc[n][3]);
                acc[n][0] = fma2(xv.y, wB0.x, acc[n][0]);
                acc[n][1] = fma2(xv.y, wB0.y, acc[n][1]);
                acc[n][2] = fma2(xv.y, wB1.x, acc[n][2]);
                acc[n][3] = fma2(xv.y, wB1.y, acc[n][3]);
            }
        }

        // epilogue per node: relu(self) [+ relu(inner matvec) when deg < 5]
        #pragma unroll 1
        for (int n = 0; n < 8; n++) {
            const int m = mbase + n;
            float r0, r1, r2, r3;
            { float lo, hi; unpack2(acc[n][0], lo, hi); r0 = fmaxf(lo + hi, 0.f); }
            { float lo, hi; unpack2(acc[n][1], lo, hi); r1 = fmaxf(lo + hi, 0.f); }
            { float lo, hi; unpack2(acc[n][2], lo, hi); r2 = fmaxf(lo + hi, 0.f); }
            { float lo, hi; unpack2(acc[n][3], lo, hi); r3 = fmaxf(lo + hi, 0.f); }

            const int deg = s_deg[m];            // warp-uniform branch
            if (deg < DD) {
                const float* wp = Wi + (size_t)deg * (FAN * CC) + c0;
                const float4 bi4 = *(const float4*)(bi + deg * CC + c0);
                u64 i0 = pack2(bi4.x, 0.f), i1 = pack2(bi4.y, 0.f),
                    i2 = pack2(bi4.z, 0.f), i3 = pack2(bi4.w, 0.f);
                #pragma unroll 2
                for (int k = 0; k < FAN; k += 2) {
                    const float4 w0 = *(const float4*)(wp + (k  )*CC);
                    const float4 w1 = *(const float4*)(wp + (k+1)*CC);
                    const u64 xp = *(const u64*)(s_X + m*FAN + k);
                    i0 = fma2(xp, pack2(w0.x, w1.x), i0);
                    i1 = fma2(xp, pack2(w0.y, w1.y), i1);
                    i2 = fma2(xp, pack2(w0.z, w1.z), i2);
                    i3 = fma2(xp, pack2(w0.w, w1.w), i3);
                }
                { float lo, hi; unpack2(i0, lo, hi); r0 += fmaxf(lo + hi, 0.f); }
                { float lo, hi; unpack2(i1, lo, hi); r1 += fmaxf(lo + hi, 0.f); }
                { float lo, hi; unpack2(i2, lo, hi); r2 += fmaxf(lo + hi, 0.f); }
                { float lo, hi; unpack2(i3, lo, hi); r3 += fmaxf(lo + hi, 0.f); }
            }

            float4 o; o.x = r0; o.y = r1; o.z = r2; o.w = r3;
            *(float4*)(out + ((size_t)b * MM + m) * CC + c0) = o;
        }
    }
}

extern "C" void kernel_launch(void* const* d_in, const int* in_sizes, int n_in,
                              void* d_out, int out_size) {
    const float* atoms = (const float*)d_in[0];
    const float* bonds = (const float*)d_in[1];
    const int*   edges = (const int*)  d_in[2];
    const float* Wi    = (const float*)d_in[3];
    const float* bi    = (const float*)d_in[4];
    const float* Ws    = (const float*)d_in[5];
    const float* bs    = (const float*)d_in[6];
    float* out = (float*)d_out;

    const int B = in_sizes[0] / (MM * FA);

    cudaFuncSetAttribute(tga_kernel,
                         cudaFuncAttributeMaxDynamicSharedMemorySize, SMEM_BYTES);
    tga_kernel<<<B, 256, SMEM_BYTES>>>(atoms, bonds, edges, Wi, bi, Ws, bs, out);
}

// round 4
// speedup vs baseline: 1.2384x; 1.1699x over previous
#include <cuda_runtime.h>
#include <cuda_bf16.h>
#include <cstdint>

#define MM 128
#define DD 5
#define FA 62
#define FB 6
#define FAN 68
#define CC 128
#define KP 88            /* padded K stride in bf16 halves (176B, conflict-free ldmatrix) */

// ---- smem byte offsets ----
#define SB_SB    0                      /* s_sb   f32 [128][6]  = 3072  */
#define SB_DEG   3072                   /* s_deg  int [128]     = 512   */
#define SB_XBUF  3584                   /* s_xbuf f32 [8][68]   = 2176  */
#define SB_AHI   5760                   /* u16 [128][88] = 22528 */
#define SB_ALO   (SB_AHI + 22528)
#define SB_BHI   (SB_ALO + 22528)
#define SB_BLO   (SB_BHI + 22528)
#define SMEM_BYTES (SB_BLO + 22528)     /* 95872 B -> 2 CTAs/SM */

typedef unsigned int u32;
typedef unsigned short u16;

__device__ __forceinline__ uint32_t smem_u32(const void* p) {
    uint32_t a;
    asm("{ .reg .u64 t; cvta.to.shared.u64 t, %1; cvt.u32.u64 %0, t; }" : "=r"(a) : "l"(p));
    return a;
}
__device__ __forceinline__ void split1(float v, u16& hi, u16& lo) {
    __nv_bfloat16 h = __float2bfloat16_rn(v);
    __nv_bfloat16 l = __float2bfloat16_rn(v - __bfloat162float(h));
    hi = __bfloat16_as_ushort(h);
    lo = __bfloat16_as_ushort(l);
}
__device__ __forceinline__ uint4 ldm_x4(uint32_t addr) {
    uint4 r;
    asm volatile("ldmatrix.sync.aligned.m8n8.x4.shared.b16 {%0,%1,%2,%3}, [%4];"
                 : "=r"(r.x), "=r"(r.y), "=r"(r.z), "=r"(r.w) : "r"(addr));
    return r;
}
__device__ __forceinline__ void mma_bf16(float4& c, const uint4& a, u32 b0, u32 b1) {
    asm volatile(
        "mma.sync.aligned.m16n8k16.row.col.f32.bf16.bf16.f32 "
        "{%0,%1,%2,%3},{%4,%5,%6,%7},{%8,%9},{%0,%1,%2,%3};"
        : "+f"(c.x), "+f"(c.y), "+f"(c.z), "+f"(c.w)
        : "r"(a.x), "r"(a.y), "r"(a.z), "r"(a.w), "r"(b0), "r"(b1));
}
__device__ __forceinline__ float bf16f(u16 v) {
    return __bfloat162float(__ushort_as_bfloat16(v));
}

__global__ __launch_bounds__(256, 2)
void tga_kernel(const float* __restrict__ atoms,
                const float* __restrict__ bonds,
                const int*   __restrict__ edges,
                const float* __restrict__ Wi,   // (D, FAN, CC)
                const float* __restrict__ bi,   // (D, CC)
                const float* __restrict__ Ws,   // (FAN, CC)
                const float* __restrict__ bs,   // (CC)
                float* __restrict__ out)        // (B, MM, CC)
{
    extern __shared__ char smem[];
    float* s_sb   = (float*)(smem + SB_SB);     // summed bonds [128][6]
    int*   s_deg  = (int*)(smem + SB_DEG);
    float* s_xbuf = (float*)(smem + SB_XBUF);   // per-warp X scratch [8][68]
    u16*   aHi = (u16*)(smem + SB_AHI);         // V tile [128][KP]
    u16*   aLo = (u16*)(smem + SB_ALO);
    u16*   bHi = (u16*)(smem + SB_BHI);         // Wt tile [128][KP] (row c, col k)
    u16*   bLo = (u16*)(smem + SB_BLO);

    const int b    = blockIdx.x;
    const int tid  = threadIdx.x;
    const int w    = tid >> 5;
    const int lane = tid & 31;

    const float* ga = atoms + (size_t)b * (MM * FA);
    const float* gb = bonds + (size_t)b * (MM * DD * FB);
    const int*   ge = edges + (size_t)b * (MM * DD);

    // ---- phase 1a: summed bonds, degree, B tiles ----
    for (int i = tid; i < MM * FB; i += 256) {
        const int m = i / FB, f = i - m * FB;
        const float* bp = gb + m * (DD * FB) + f;
        s_sb[i] = bp[0] + bp[6] + bp[12] + bp[18] + bp[24];
    }
    if (tid < MM) {
        const int* ep = ge + tid * DD;
        s_deg[tid] = (ep[0] >= 0) + (ep[1] >= 0) + (ep[2] >= 0) + (ep[3] >= 0) + (ep[4] >= 0);
    }
    // B: bHi/bLo[c*KP + k] = split(Ws[k][c]) ; k=68 -> bs[c]; k 69..79 -> 0
    for (int i = tid; i < 80 * CC; i += 256) {
        const int k = i >> 7, c = i & 127;
        float v = 0.f;
        if (k < FAN)       v = Ws[k * CC + c];
        else if (k == FAN) v = bs[c];
        u16 h, l; split1(v, h, l);
        bHi[c * KP + k] = h;
        bLo[c * KP + k] = l;
    }
    __syncthreads();

    // ---- phase 1b: A tiles: V = [atoms | summed_bonds | 1 | 0...] ----
    for (int i = tid; i < MM * 40; i += 256) {
        const int m = i / 40, kp = i - m * 40, k = 2 * kp;
        float v0 = 0.f, v1 = 0.f;
        if (k < FA) {
            const float2 t = *(const float2*)(ga + m * FA + k);
            v0 = t.x; v1 = t.y;
        } else if (k < FAN) {
            v0 = s_sb[m * FB + (k - FA)];
            v1 = s_sb[m * FB + (k - FA + 1)];
        } else if (k == FAN) {
            v0 = 1.f;
        }
        u16 h0, l0, h1, l1;
        split1(v0, h0, l0); split1(v1, h1, l1);
        *(u32*)(aHi + m * KP + k) = (u32)h0 | ((u32)h1 << 16);
        *(u32*)(aLo + m * KP + k) = (u32)l0 | ((u32)l1 << 16);
    }
    __syncthreads();

    // ---- phase 2: warp-tiled MMA: warp w -> rows [16w, 16w+16), all 128 cols ----
    const int m0 = w * 16;
    const u32 aHiAddr = smem_u32(aHi);
    const u32 aLoAddr = smem_u32(aLo);
    const u32 bHiAddr = smem_u32(bHi);
    const u32 bLoAddr = smem_u32(bLo);
    // ldmatrix lane address components
    const int aRow = m0 + (lane & 7) + ((lane >> 3) & 1) * 8;
    const int aColOff = (lane >> 4) * 8;
    const int bRowOff = (lane & 7) + ((lane >> 4) & 1) * 8;
    const int bColOff = ((lane >> 3) & 1) * 8;

    #pragma unroll 1
    for (int h = 0; h < 2; h++) {
        float4 acc[8];
        #pragma unroll
        for (int j = 0; j < 8; j++) acc[j] = make_float4(0.f, 0.f, 0.f, 0.f);

        #pragma unroll 1
        for (int kt = 0; kt < 5; kt++) {
            const int k0 = kt * 16;
            const uint4 a_hi = ldm_x4(aHiAddr + (aRow * KP + k0 + aColOff) * 2);
            const uint4 a_lo = ldm_x4(aLoAddr + (aRow * KP + k0 + aColOff) * 2);
            #pragma unroll
            for (int g = 0; g < 4; g++) {
                const int n0 = h * 64 + g * 16;
                const u32 boff = ((n0 + bRowOff) * KP + k0 + bColOff) * 2;
                const uint4 b_hi = ldm_x4(bHiAddr + boff);
                const uint4 b_lo = ldm_x4(bLoAddr + boff);
                mma_bf16(acc[2*g],   a_hi, b_hi.x, b_hi.y);
                mma_bf16(acc[2*g+1], a_hi, b_hi.z, b_hi.w);
                mma_bf16(acc[2*g],   a_hi, b_lo.x, b_lo.y);
                mma_bf16(acc[2*g+1], a_hi, b_lo.z, b_lo.w);
                mma_bf16(acc[2*g],   a_lo, b_hi.x, b_hi.y);
                mma_bf16(acc[2*g+1], a_lo, b_hi.z, b_hi.w);
            }
        }

        // epilogue: relu + store. c-frag: rows m0 + lane/4 (+8), cols n0 + 2*(lane&3)
        const int row0 = m0 + (lane >> 2);
        float* ob = out + (size_t)b * (MM * CC);
        #pragma unroll
        for (int j = 0; j < 8; j++) {
            const int c = h * 64 + j * 8 + 2 * (lane & 3);
            float2 lo2, hi2;
            lo2.x = fmaxf(acc[j].x, 0.f); lo2.y = fmaxf(acc[j].y, 0.f);
            hi2.x = fmaxf(acc[j].z, 0.f); hi2.y = fmaxf(acc[j].w, 0.f);
            *(float2*)(ob + row0 * CC + c)       = lo2;
            *(float2*)(ob + (row0 + 8) * CC + c) = hi2;
        }
    }
    __syncwarp();

    // ---- phase 3: rare inner matvec (deg<5 only, ~3.8% of nodes) ----
    for (int mi = 0; mi < 16; mi++) {
        const int m = w * 16 + mi;
        const int deg = s_deg[m];            // warp-uniform
        if (deg < DD) {
            const int e0 = ge[m*DD+0], e1 = ge[m*DD+1], e2 = ge[m*DD+2],
                      e3 = ge[m*DD+3], e4 = ge[m*DD+4];
            // build X = [summed_atoms | summed_bonds] in per-warp scratch
            #pragma unroll
            for (int rep = 0; rep < 3; rep++) {
                const int f = lane + rep * 32;
                if (f < FA) {
                    float s = 0.f;
                    if (e0 >= 0) s += bf16f(aHi[e0*KP + f]) + bf16f(aLo[e0*KP + f]);
                    if (e1 >= 0) s += bf16f(aHi[e1*KP + f]) + bf16f(aLo[e1*KP + f]);
                    if (e2 >= 0) s += bf16f(aHi[e2*KP + f]) + bf16f(aLo[e2*KP + f]);
                    if (e3 >= 0) s += bf16f(aHi[e3*KP + f]) + bf16f(aLo[e3*KP + f]);
                    if (e4 >= 0) s += bf16f(aHi[e4*KP + f]) + bf16f(aLo[e4*KP + f]);
                    s_xbuf[w * FAN + f] = s;
                } else if (f < FAN) {
                    s_xbuf[w * FAN + f] = s_sb[m * FB + (f - FA)];
                }
            }
            __syncwarp();
            const int c = lane * 4;
            const float* wp = Wi + ((size_t)deg * FAN) * CC + c;
            float4 acc = *(const float4*)(bi + deg * CC + c);
            const float* xr = s_xbuf + w * FAN;
            #pragma unroll 4
            for (int k = 0; k < FAN; k++) {
                const float xv = xr[k];
                const float4 w4 = *(const float4*)(wp + k * CC);
                acc.x += xv * w4.x; acc.y += xv * w4.y;
                acc.z += xv * w4.z; acc.w += xv * w4.w;
            }
            float4* outp = (float4*)(out + ((size_t)b * MM + m) * CC + c);
            float4 o = *outp;
            o.x += fmaxf(acc.x, 0.f); o.y += fmaxf(acc.y, 0.f);
            o.z += fmaxf(acc.z, 0.f); o.w += fmaxf(acc.w, 0.f);
            *outp = o;
            __syncwarp();
        }
    }
}

extern "C" void kernel_launch(void* const* d_in, const int* in_sizes, int n_in,
                              void* d_out, int out_size) {
    const float* atoms = (const float*)d_in[0];
    const float* bonds = (const float*)d_in[1];
    const int*   edges = (const int*)  d_in[2];
    const float* Wi    = (const float*)d_in[3];
    const float* bi    = (const float*)d_in[4];
    const float* Ws    = (const float*)d_in[5];
    const float* bs    = (const float*)d_in[6];
    float* out = (float*)d_out;

    const int B = in_sizes[0] / (MM * FA);

    cudaFuncSetAttribute(tga_kernel,
                         cudaFuncAttributeMaxDynamicSharedMemorySize, SMEM_BYTES);
    tga_kernel<<<B, 256, SMEM_BYTES>>>(atoms, bonds, edges, Wi, bi, Ws, bs, out);
}

// round 5
// speedup vs baseline: 1.9505x; 1.5751x over previous
#include <cuda_runtime.h>
#include <cuda_bf16.h>
#include <cstdint>

#define MM 128
#define DD 5
#define FA 62
#define FB 6
#define FAN 68
#define CC 128
#define KP 88            /* A-tile K stride in halves (176B, conflict-free ldmatrix) */

// ---- smem byte offsets ----
#define SB_SB    0                      /* s_sb   f32 [128][6]  = 3072  */
#define SB_DEG   3072                   /* s_deg  int [128]     = 512   */
#define SB_XBUF  3584                   /* s_xbuf f32 [8][68]   = 2176  */
#define SB_AHI   5760                   /* u16 [128][88] = 22528 */
#define SB_ALO   (SB_AHI + 22528)
#define SMEM_BYTES (SB_ALO + 22528)     /* 50816 B -> 4 CTAs/SM */

typedef unsigned int u32;
typedef unsigned short u16;
typedef unsigned long long u64;

// Pre-split B fragments: index = (kt*16 + n8)*32 + lane ; kt in [0,5), n8 in [0,16)
__device__ u64 g_bhi[2560];
__device__ u64 g_blo[2560];

__device__ __forceinline__ uint32_t smem_u32(const void* p) {
    uint32_t a;
    asm("{ .reg .u64 t; cvta.to.shared.u64 t, %1; cvt.u32.u64 %0, t; }" : "=r"(a) : "l"(p));
    return a;
}
__device__ __forceinline__ void split1(float v, u16& hi, u16& lo) {
    __nv_bfloat16 h = __float2bfloat16_rn(v);
    __nv_bfloat16 l = __float2bfloat16_rn(v - __bfloat162float(h));
    hi = __bfloat16_as_ushort(h);
    lo = __bfloat16_as_ushort(l);
}
__device__ __forceinline__ uint4 ldm_x4(uint32_t addr) {
    uint4 r;
    asm volatile("ldmatrix.sync.aligned.m8n8.x4.shared.b16 {%0,%1,%2,%3}, [%4];"
                 : "=r"(r.x), "=r"(r.y), "=r"(r.z), "=r"(r.w) : "r"(addr));
    return r;
}
__device__ __forceinline__ void mma_bf16(float4& c, const uint4& a, u32 b0, u32 b1) {
    asm volatile(
        "mma.sync.aligned.m16n8k16.row.col.f32.bf16.bf16.f32 "
        "{%0,%1,%2,%3},{%4,%5,%6,%7},{%8,%9},{%0,%1,%2,%3};"
        : "+f"(c.x), "+f"(c.y), "+f"(c.z), "+f"(c.w)
        : "r"(a.x), "r"(a.y), "r"(a.z), "r"(a.w), "r"(b0), "r"(b1));
}
__device__ __forceinline__ float bf16f(u16 v) {
    return __bfloat162float(__ushort_as_bfloat16(v));
}

// ---- setup kernel: split Ws|bs into fragment-ordered hi/lo bf16 ----
__global__ void pack_b_kernel(const float* __restrict__ Ws, const float* __restrict__ bs) {
    const int idx = blockIdx.x * blockDim.x + threadIdx.x;
    if (idx >= 2560) return;
    const int l    = idx & 31;
    const int tile = idx >> 5;         // kt*16 + n8
    const int kt   = tile >> 4;
    const int n8   = tile & 15;
    const int c    = l >> 2, t = l & 3;
    const int n    = n8 * 8 + c;
    const int k0   = kt * 16 + 2 * t;
    const int ks[4] = { k0, k0 + 1, k0 + 8, k0 + 9 };
    u16 h[4], lo[4];
    #pragma unroll
    for (int q = 0; q < 4; q++) {
        const int k = ks[q];
        float v = 0.f;
        if (k < FAN)       v = Ws[k * CC + n];
        else if (k == FAN) v = bs[n];
        split1(v, h[q], lo[q]);
    }
    const u32 h0 = (u32)h[0]  | ((u32)h[1]  << 16);
    const u32 h1 = (u32)h[2]  | ((u32)h[3]  << 16);
    const u32 l0 = (u32)lo[0] | ((u32)lo[1] << 16);
    const u32 l1 = (u32)lo[2] | ((u32)lo[3] << 16);
    g_bhi[idx] = (u64)h0 | ((u64)h1 << 32);
    g_blo[idx] = (u64)l0 | ((u64)l1 << 32);
}

__global__ __launch_bounds__(256, 4)
void tga_kernel(const float* __restrict__ atoms,
                const float* __restrict__ bonds,
                const int*   __restrict__ edges,
                const float* __restrict__ Wi,   // (D, FAN, CC)
                const float* __restrict__ bi,   // (D, CC)
                float* __restrict__ out)        // (B, MM, CC)
{
    extern __shared__ char smem[];
    float* s_sb   = (float*)(smem + SB_SB);     // summed bonds [128][6]
    int*   s_deg  = (int*)(smem + SB_DEG);
    float* s_xbuf = (float*)(smem + SB_XBUF);   // per-warp X scratch [8][68]
    u16*   aHi = (u16*)(smem + SB_AHI);         // V tile [128][KP]
    u16*   aLo = (u16*)(smem + SB_ALO);

    const int b    = blockIdx.x;
    const int tid  = threadIdx.x;
    const int w    = tid >> 5;
    const int lane = tid & 31;

    const float* ga = atoms + (size_t)b * (MM * FA);
    const float* gb = bonds + (size_t)b * (MM * DD * FB);
    const int*   ge = edges + (size_t)b * (MM * DD);

    // ---- phase 1a: summed bonds + degree ----
    for (int i = tid; i < MM * FB; i += 256) {
        const int m = i / FB, f = i - m * FB;
        const float* bp = gb + m * (DD * FB) + f;
        s_sb[i] = bp[0] + bp[6] + bp[12] + bp[18] + bp[24];
    }
    if (tid < MM) {
        const int* ep = ge + tid * DD;
        s_deg[tid] = (ep[0] >= 0) + (ep[1] >= 0) + (ep[2] >= 0) + (ep[3] >= 0) + (ep[4] >= 0);
    }
    __syncthreads();

    // ---- phase 1b: A tiles: V = [atoms | summed_bonds | 1 | 0...] ----
    for (int i = tid; i < MM * 40; i += 256) {
        const int m = i / 40, kp = i - m * 40, k = 2 * kp;
        float v0 = 0.f, v1 = 0.f;
        if (k < FA) {
            const float2 t = *(const float2*)(ga + m * FA + k);
            v0 = t.x; v1 = t.y;
        } else if (k < FAN) {
            v0 = s_sb[m * FB + (k - FA)];
            v1 = s_sb[m * FB + (k - FA + 1)];
        } else if (k == FAN) {
            v0 = 1.f;
        }
        u16 h0, l0, h1, l1;
        split1(v0, h0, l0); split1(v1, h1, l1);
        *(u32*)(aHi + m * KP + k) = (u32)h0 | ((u32)h1 << 16);
        *(u32*)(aLo + m * KP + k) = (u32)l0 | ((u32)l1 << 16);
    }
    __syncthreads();

    // ---- phase 2: warp w -> rows [16w,16w+16); cols in 4 quarters of 32 ----
    const int m0 = w * 16;
    const u32 aHiAddr = smem_u32(aHi);
    const u32 aLoAddr = smem_u32(aLo);
    const int aRow = m0 + (lane & 7) + ((lane >> 3) & 1) * 8;
    const int aColOff = (lane >> 4) * 8;
    float* ob = out + (size_t)b * (MM * CC);
    const int row0 = m0 + (lane >> 2);

    #pragma unroll 1
    for (int h = 0; h < 4; h++) {
        float4 acc[4];
        #pragma unroll
        for (int j = 0; j < 4; j++) acc[j] = make_float4(0.f, 0.f, 0.f, 0.f);

        #pragma unroll 1
        for (int kt = 0; kt < 5; kt++) {
            const int k0 = kt * 16;
            const uint4 a_hi = ldm_x4(aHiAddr + (aRow * KP + k0 + aColOff) * 2);
            const uint4 a_lo = ldm_x4(aLoAddr + (aRow * KP + k0 + aColOff) * 2);
            const u64* bh = g_bhi + (kt * 16 + h * 4) * 32 + lane;
            const u64* bl = g_blo + (kt * 16 + h * 4) * 32 + lane;
            u64 vh[4], vl[4];
            #pragma unroll
            for (int j = 0; j < 4; j++) { vh[j] = bh[j * 32]; vl[j] = bl[j * 32]; }
            #pragma unroll
            for (int j = 0; j < 4; j++)
                mma_bf16(acc[j], a_hi, (u32)vh[j], (u32)(vh[j] >> 32));
            #pragma unroll
            for (int j = 0; j < 4; j++)
                mma_bf16(acc[j], a_hi, (u32)vl[j], (u32)(vl[j] >> 32));
            #pragma unroll
            for (int j = 0; j < 4; j++)
                mma_bf16(acc[j], a_lo, (u32)vh[j], (u32)(vh[j] >> 32));
        }

        // epilogue quarter: relu + store
        #pragma unroll
        for (int j = 0; j < 4; j++) {
            const int c = h * 32 + j * 8 + 2 * (lane & 3);
            float2 lo2, hi2;
            lo2.x = fmaxf(acc[j].x, 0.f); lo2.y = fmaxf(acc[j].y, 0.f);
            hi2.x = fmaxf(acc[j].z, 0.f); hi2.y = fmaxf(acc[j].w, 0.f);
            *(float2*)(ob + row0 * CC + c)       = lo2;
            *(float2*)(ob + (row0 + 8) * CC + c) = hi2;
        }
    }
    __syncwarp();

    // ---- phase 3: rare inner matvec (deg<5 only, ~3.8% of nodes) ----
    for (int mi = 0; mi < 16; mi++) {
        const int m = w * 16 + mi;
        const int deg = s_deg[m];            // warp-uniform
        if (deg < DD) {
            const int e0 = ge[m*DD+0], e1 = ge[m*DD+1], e2 = ge[m*DD+2],
                      e3 = ge[m*DD+3], e4 = ge[m*DD+4];
            #pragma unroll
            for (int rep = 0; rep < 3; rep++) {
                const int f = lane + rep * 32;
                if (f < FA) {
                    float s = 0.f;
                    if (e0 >= 0) s += bf16f(aHi[e0*KP + f]) + bf16f(aLo[e0*KP + f]);
                    if (e1 >= 0) s += bf16f(aHi[e1*KP + f]) + bf16f(aLo[e1*KP + f]);
                    if (e2 >= 0) s += bf16f(aHi[e2*KP + f]) + bf16f(aLo[e2*KP + f]);
                    if (e3 >= 0) s += bf16f(aHi[e3*KP + f]) + bf16f(aLo[e3*KP + f]);
                    if (e4 >= 0) s += bf16f(aHi[e4*KP + f]) + bf16f(aLo[e4*KP + f]);
                    s_xbuf[w * FAN + f] = s;
                } else if (f < FAN) {
                    s_xbuf[w * FAN + f] = s_sb[m * FB + (f - FA)];
                }
            }
            __syncwarp();
            const int c = lane * 4;
            const float* wp = Wi + ((size_t)deg * FAN) * CC + c;
            float4 acc = *(const float4*)(bi + deg * CC + c);
            const float* xr = s_xbuf + w * FAN;
            #pragma unroll 4
            for (int k = 0; k < FAN; k++) {
                const float xv = xr[k];
                const float4 w4 = *(const float4*)(wp + k * CC);
                acc.x += xv * w4.x; acc.y += xv * w4.y;
                acc.z += xv * w4.z; acc.w += xv * w4.w;
            }
            float4* outp = (float4*)(out + ((size_t)b * MM + m) * CC + c);
            float4 o = *outp;
            o.x += fmaxf(acc.x, 0.f); o.y += fmaxf(acc.y, 0.f);
            o.z += fmaxf(acc.z, 0.f); o.w += fmaxf(acc.w, 0.f);
            *outp = o;
            __syncwarp();
        }
    }
}

extern "C" void kernel_launch(void* const* d_in, const int* in_sizes, int n_in,
                              void* d_out, int out_size) {
    const float* atoms = (const float*)d_in[0];
    const float* bonds = (const float*)d_in[1];
    const int*   edges = (const int*)  d_in[2];
    const float* Wi    = (const float*)d_in[3];
    const float* bi    = (const float*)d_in[4];
    const float* Ws    = (const float*)d_in[5];
    const float* bs    = (const float*)d_in[6];
    float* out = (float*)d_out;

    const int B = in_sizes[0] / (MM * FA);

    pack_b_kernel<<<10, 256>>>(Ws, bs);

    cudaFuncSetAttribute(tga_kernel,
                         cudaFuncAttributeMaxDynamicSharedMemorySize, SMEM_BYTES);
    tga_kernel<<<B, 256, SMEM_BYTES>>>(atoms, bonds, edges, Wi, bi, out);
}

// round 7
// speedup vs baseline: 2.6088x; 1.3375x over previous
#include <cuda_runtime.h>
#include <cuda_fp16.h>
#include <cstdint>

#define MM 128
#define DD 5
#define FA 62
#define FB 6
#define FAN 68
#define CC 128
#define KP 88            /* A-tile K stride in halves (176B, conflict-free ldmatrix) */

// ---- smem byte offsets ----
#define SB_SB    0                      /* s_sb   f32 [128][6]  = 3072  */
#define SB_DEG   3072                   /* s_deg  int [128]     = 512   */
#define SB_XBUF  3584                   /* s_xbuf f32 [8][68]   = 2176  */
#define SB_A     5760                   /* u16 [128][88] = 22528 */
#define SMEM_BYTES (SB_A + 22528)       /* 28288 B */

typedef unsigned int u32;
typedef unsigned short u16;
typedef unsigned long long u64;

// Pre-packed fp16 B fragments: index = (kt*16 + n8)*32 + lane ; kt in [0,5), n8 in [0,16)
__device__ u64 g_bf[2560];

__device__ __forceinline__ uint32_t smem_u32(const void* p) {
    uint32_t a;
    asm("{ .reg .u64 t; cvta.to.shared.u64 t, %1; cvt.u32.u64 %0, t; }" : "=r"(a) : "l"(p));
    return a;
}
__device__ __forceinline__ uint4 ldm_x4(uint32_t addr) {
    uint4 r;
    asm volatile("ldmatrix.sync.aligned.m8n8.x4.shared.b16 {%0,%1,%2,%3}, [%4];"
                 : "=r"(r.x), "=r"(r.y), "=r"(r.z), "=r"(r.w) : "r"(addr));
    return r;
}
__device__ __forceinline__ void mma_f16(float4& c, const uint4& a, u32 b0, u32 b1) {
    asm volatile(
        "mma.sync.aligned.m16n8k16.row.col.f32.f16.f16.f32 "
        "{%0,%1,%2,%3},{%4,%5,%6,%7},{%8,%9},{%0,%1,%2,%3};"
        : "+f"(c.x), "+f"(c.y), "+f"(c.z), "+f"(c.w)
        : "r"(a.x), "r"(a.y), "r"(a.z), "r"(a.w), "r"(b0), "r"(b1));
}
__device__ __forceinline__ u16 h16(float v) {
    return __half_as_ushort(__float2half_rn(v));
}
__device__ __forceinline__ float f16f(u16 v) {
    return __half2float(__ushort_as_half(v));
}

// ---- setup kernel: pack Ws|bs into fragment-ordered fp16 ----
__global__ void pack_b_kernel(const float* __restrict__ Ws, const float* __restrict__ bs) {
    const int idx = blockIdx.x * blockDim.x + threadIdx.x;
    if (idx >= 2560) return;
    const int l    = idx & 31;
    const int tile = idx >> 5;         // kt*16 + n8
    const int kt   = tile >> 4;
    const int n8   = tile & 15;
    const int c    = l >> 2, t = l & 3;
    const int n    = n8 * 8 + c;
    const int k0   = kt * 16 + 2 * t;
    const int ks[4] = { k0, k0 + 1, k0 + 8, k0 + 9 };
    u16 h[4];
    #pragma unroll
    for (int q = 0; q < 4; q++) {
        const int k = ks[q];
        float v = 0.f;
        if (k < FAN)       v = Ws[k * CC + n];
        else if (k == FAN) v = bs[n];
        h[q] = h16(v);
    }
    g_bf[idx] = (u64)((u32)h[0] | ((u32)h[1] << 16))
              | ((u64)((u32)h[2] | ((u32)h[3] << 16)) << 32);
}

__global__ __launch_bounds__(256, 5)
void tga_kernel(const float* __restrict__ atoms,
                const float* __restrict__ bonds,
                const int*   __restrict__ edges,
                const float* __restrict__ Wi,   // (D, FAN, CC)
                const float* __restrict__ bi,   // (D, CC)
                float* __restrict__ out)        // (B, MM, CC)
{
    extern __shared__ char smem[];
    float* s_sb   = (float*)(smem + SB_SB);     // summed bonds [128][6]
    int*   s_deg  = (int*)(smem + SB_DEG);
    float* s_xbuf = (float*)(smem + SB_XBUF);   // per-warp X scratch [8][68]
    u16*   aF     = (u16*)(smem + SB_A);        // V tile fp16 [128][KP]

    const int b    = blockIdx.x;
    const int tid  = threadIdx.x;
    const int w    = tid >> 5;
    const int lane = tid & 31;

    const float* ga = atoms + (size_t)b * (MM * FA);
    const float* gb = bonds + (size_t)b * (MM * DD * FB);
    const int*   ge = edges + (size_t)b * (MM * DD);

    // ---- phase 1a: summed bonds + degree ----
    for (int i = tid; i < MM * FB; i += 256) {
        const int m = i / FB, f = i - m * FB;
        const float* bp = gb + m * (DD * FB) + f;
        s_sb[i] = bp[0] + bp[6] + bp[12] + bp[18] + bp[24];
    }
    if (tid < MM) {
        const int* ep = ge + tid * DD;
        s_deg[tid] = (ep[0] >= 0) + (ep[1] >= 0) + (ep[2] >= 0) + (ep[3] >= 0) + (ep[4] >= 0);
    }
    __syncthreads();

    // ---- phase 1b: A tile: V = [atoms | summed_bonds | 1 | 0...] as fp16 ----
    for (int i = tid; i < MM * 44; i += 256) {
        const int m = i / 44, kp = i - m * 44, k = 2 * kp;
        float v0 = 0.f, v1 = 0.f;
        if (k < FA) {
            const float2 t = *(const float2*)(ga + m * FA + k);
            v0 = t.x; v1 = t.y;
        } else if (k < FAN) {
            v0 = s_sb[m * FB + (k - FA)];
            v1 = s_sb[m * FB + (k - FA + 1)];
        } else if (k == FAN) {
            v0 = 1.f;
        }
        *(u32*)(aF + m * KP + k) = (u32)h16(v0) | ((u32)h16(v1) << 16);
    }
    __syncthreads();

    // ---- phase 2: warp w -> rows [16w,16w+16); cols in 4 quarters of 32 ----
    const int m0 = w * 16;
    const u32 aAddr = smem_u32(aF);
    const int aRow = m0 + (lane & 7) + ((lane >> 3) & 1) * 8;
    const int aColOff = (lane >> 4) * 8;
    float* ob = out + (size_t)b * (MM * CC);
    const int row0 = m0 + (lane >> 2);

    #pragma unroll 1
    for (int h = 0; h < 4; h++) {
        float4 acc[4];
        #pragma unroll
        for (int j = 0; j < 4; j++) acc[j] = make_float4(0.f, 0.f, 0.f, 0.f);

        #pragma unroll
        for (int kt = 0; kt < 5; kt++) {
            const int k0 = kt * 16;
            const uint4 a = ldm_x4(aAddr + (aRow * KP + k0 + aColOff) * 2);
            const u64* bp = g_bf + (kt * 16 + h * 4) * 32 + lane;
            u64 v[4];
            #pragma unroll
            for (int j = 0; j < 4; j++) v[j] = bp[j * 32];
            #pragma unroll
            for (int j = 0; j < 4; j++)
                mma_f16(acc[j], a, (u32)v[j], (u32)(v[j] >> 32));
        }

        // epilogue quarter: relu + store
        #pragma unroll
        for (int j = 0; j < 4; j++) {
            const int c = h * 32 + j * 8 + 2 * (lane & 3);
            float2 lo2, hi2;
            lo2.x = fmaxf(acc[j].x, 0.f); lo2.y = fmaxf(acc[j].y, 0.f);
            hi2.x = fmaxf(acc[j].z, 0.f); hi2.y = fmaxf(acc[j].w, 0.f);
            *(float2*)(ob + row0 * CC + c)       = lo2;
            *(float2*)(ob + (row0 + 8) * CC + c) = hi2;
        }
    }
    __syncwarp();

    // ---- phase 3: rare inner matvec (deg<5 only, ~3.8% of nodes) ----
    for (int mi = 0; mi < 16; mi++) {
        const int m = w * 16 + mi;
        const int deg = s_deg[m];            // warp-uniform
        if (deg < DD) {
            const int e0 = ge[m*DD+0], e1 = ge[m*DD+1], e2 = ge[m*DD+2],
                      e3 = ge[m*DD+3], e4 = ge[m*DD+4];
            // build X = [summed_atoms | summed_bonds] in per-warp scratch
            #pragma unroll
            for (int rep = 0; rep < 3; rep++) {
                const int f = lane + rep * 32;
                if (f < FA) {
                    float s = 0.f;
                    if (e0 >= 0) s += f16f(aF[e0*KP + f]);
                    if (e1 >= 0) s += f16f(aF[e1*KP + f]);
                    if (e2 >= 0) s += f16f(aF[e2*KP + f]);
                    if (e3 >= 0) s += f16f(aF[e3*KP + f]);
                    if (e4 >= 0) s += f16f(aF[e4*KP + f]);
                    s_xbuf[w * FAN + f] = s;
                } else if (f < FAN) {
                    s_xbuf[w * FAN + f] = s_sb[m * FB + (f - FA)];
                }
            }
            __syncwarp();
            const int c = lane * 4;
            const float* wp = Wi + ((size_t)deg * FAN) * CC + c;
            float4 acc = *(const float4*)(bi + deg * CC + c);
            const float* xr = s_xbuf + w * FAN;
            #pragma unroll 4
            for (int k = 0; k < FAN; k++) {
                const float xv = xr[k];
                const float4 w4 = *(const float4*)(wp + k * CC);
                acc.x += xv * w4.x; acc.y += xv * w4.y;
                acc.z += xv * w4.z; acc.w += xv * w4.w;
            }
            float4* outp = (float4*)(out + ((size_t)b * MM + m) * CC + c);
            float4 o = *outp;
            o.x += fmaxf(acc.x, 0.f); o.y += fmaxf(acc.y, 0.f);
            o.z += fmaxf(acc.z, 0.f); o.w += fmaxf(acc.w, 0.f);
            *outp = o;
            __syncwarp();
        }
    }
}

extern "C" void kernel_launch(void* const* d_in, const int* in_sizes, int n_in,
                              void* d_out, int out_size) {
    const float* atoms = (const float*)d_in[0];
    const float* bonds = (const float*)d_in[1];
    const int*   edges = (const int*)  d_in[2];
    const float* Wi    = (const float*)d_in[3];
    const float* bi    = (const float*)d_in[4];
    const float* Ws    = (const float*)d_in[5];
    const float* bs    = (const float*)d_in[6];
    float* out = (float*)d_out;

    const int B = in_sizes[0] / (MM * FA);

    pack_b_kernel<<<10, 256>>>(Ws, bs);

    cudaFuncSetAttribute(tga_kernel,
                         cudaFuncAttributeMaxDynamicSharedMemorySize, SMEM_BYTES);
    tga_kernel<<<B, 256, SMEM_BYTES>>>(atoms, bonds, edges, Wi, bi, out);
}